// round 1
// baseline (speedup 1.0000x reference)
#include <cuda_runtime.h>
#include <cuda_bf16.h>
#include <math.h>

// Problem dims
#define BB 2
#define SS 2048
#define DD 1024
#define HH 16
#define DH 64
#define RR 256
#define NCEXP 16
#define NKK 4096
#define KRR 256
#define TOPK_N 8

// ---------------- scratch (device globals; no runtime alloc) ----------------
__device__ float g_nx [BB*SS*DD];
__device__ float g_nx2[BB*SS*DD];
__device__ float g_h  [BB*SS*RR];
__device__ float g_Qm [BB*SS*RR];
__device__ float g_Q  [BB*SS*DD];
__device__ float g_K  [BB*SS*DD];
__device__ float g_V  [BB*SS*DD];
__device__ float g_ao [BB*SS*DD];
__device__ float g_x1 [BB*SS*DD];
__device__ float g_ms [BB*SS*NKK];
__device__ float g_sc [BB*DD*RR];
__device__ float g_mc [BB*DD*RR];
__device__ float g_eq [BB*RR*DD];
__device__ float g_ek [BB*RR*DD];
__device__ float g_ev [BB*RR*DD];
__device__ float g_pref[BB*SS*64];   // per-token importance-weighted softmax, up to 4 routers
__device__ float g_w  [5*BB*16];     // pooled, normalized router weights: [router][b][16]

__device__ __forceinline__ float warp_sum(float v){
#pragma unroll
    for (int o=16;o;o>>=1) v += __shfl_xor_sync(0xffffffffu, v, o);
    return v;
}

// ---------------- LayerNorm: one block per row ----------------
__global__ __launch_bounds__(256) void ln_kernel(const float* __restrict__ X,
                                                 const float* __restrict__ G,
                                                 const float* __restrict__ Bt,
                                                 float* __restrict__ O){
    int row = blockIdx.x, tid = threadIdx.x;
    const float* xr = X + (long)row*DD + tid*4;
    float4 v = *(const float4*)xr;
    float s = v.x+v.y+v.z+v.w;
    float q = v.x*v.x+v.y*v.y+v.z*v.z+v.w*v.w;
    __shared__ float rs[8], rq[8];
    __shared__ float stats[2];
    s = warp_sum(s); q = warp_sum(q);
    int wid = tid>>5, lane = tid&31;
    if (lane==0){ rs[wid]=s; rq[wid]=q; }
    __syncthreads();
    if (tid==0){
        float Sm=0.f, Qm=0.f;
#pragma unroll
        for (int i=0;i<8;i++){ Sm+=rs[i]; Qm+=rq[i]; }
        float mu  = Sm*(1.f/(float)DD);
        float var = Qm*(1.f/(float)DD) - mu*mu;
        stats[0]=mu; stats[1]=rsqrtf(var + 1e-5f);
    }
    __syncthreads();
    float mu = stats[0], rstd = stats[1];
    float4 g4 = *(const float4*)(G  + tid*4);
    float4 b4 = *(const float4*)(Bt + tid*4);
    float4 o4;
    o4.x = (v.x-mu)*rstd*g4.x + b4.x;
    o4.y = (v.y-mu)*rstd*g4.y + b4.y;
    o4.z = (v.z-mu)*rstd*g4.z + b4.z;
    o4.w = (v.w-mu)*rstd*g4.w + b4.w;
    *(float4*)(O + (long)row*DD + tid*4) = o4;
}

// ---------------- router: per-token logits -> softmax -> imp-weighted write ----------------
__global__ __launch_bounds__(256) void router_kernel(const float* __restrict__ NX,
                                                     const float* __restrict__ IMP,
                                                     const float* __restrict__ W0,
                                                     const float* __restrict__ W1,
                                                     const float* __restrict__ W2,
                                                     const float* __restrict__ W3,
                                                     int NR){
    int token = blockIdx.x;
    int tid = threadIdx.x, wid = tid>>5, lane = tid&31;
    __shared__ float xs[DD];
    __shared__ float logits[64];
    *(float4*)&xs[tid*4] = *(const float4*)(NX + (long)token*DD + tid*4);
    __syncthreads();
    const float* Ws[4] = {W0,W1,W2,W3};
    for (int l = wid; l < NR*16; l += 8){
        const float* wrow = Ws[l>>4] + (long)(l&15)*DD;
        float p = 0.f;
#pragma unroll
        for (int d0=0; d0<DD; d0+=128){
            float4 xv = *(const float4*)&xs[d0 + lane*4];
            float4 wv = *(const float4*)(wrow + d0 + lane*4);
            p += xv.x*wv.x + xv.y*wv.y + xv.z*wv.z + xv.w*wv.w;
        }
        p = warp_sum(p);
        if (lane==0) logits[l] = p;
    }
    __syncthreads();
    if (tid < NR){
        float im = IMP[token];
        float mx = -1e30f;
#pragma unroll
        for (int n=0;n<16;n++) mx = fmaxf(mx, logits[tid*16+n]);
        float e[16]; float sum = 0.f;
#pragma unroll
        for (int n=0;n<16;n++){ e[n] = __expf(logits[tid*16+n]-mx); sum += e[n]; }
        float inv = im / sum;
#pragma unroll
        for (int n=0;n<16;n++) g_pref[(long)token*64 + tid*16 + n] = e[n]*inv;
    }
}

// deterministic pooled sum over sequence: one block per (router-expert, batch)
__global__ __launch_bounds__(256) void pool_w(int base, int NR){
    int ln = blockIdx.x;          // 0..NR*16-1
    int b  = blockIdx.y;
    int tid = threadIdx.x;
    float s = 0.f;
    for (int t=tid; t<SS; t+=256)
        s += g_pref[((long)(b*SS+t))*64 + ln];
    s = warp_sum(s);
    __shared__ float rs[8];
    if ((tid&31)==0) rs[tid>>5] = s;
    __syncthreads();
    if (tid==0){
        float S=0.f;
#pragma unroll
        for (int i=0;i<8;i++) S += rs[i];
        g_w[(base + (ln>>4))*32 + b*16 + (ln&15)] = S;
    }
    (void)NR;
}

__global__ void norm_w(int base, int NR){
    int i = threadIdx.x;
    if (i < NR*BB){
        int ri = base + i/BB, b = i%BB;
        float s = 0.f;
#pragma unroll
        for (int n=0;n<16;n++) s += g_w[ri*32 + b*16 + n];
        s += 1e-8f;
        float inv = 1.f/s;
#pragma unroll
        for (int n=0;n<16;n++) g_w[ri*32 + b*16 + n] *= inv;
    }
}

// ---------------- expert mixing ----------------
__global__ __launch_bounds__(256) void mix_compress(const float* __restrict__ CN,
                                                    float* __restrict__ outp, int ri){
    long i = (long)blockIdx.x*256 + threadIdx.x;   // over BB*DD*RR
    int b = (int)(i >> 18);                        // DD*RR = 262144
    int j = (int)(i & 262143);
    float a = 0.f;
#pragma unroll
    for (int n=0;n<16;n++) a += g_w[ri*32 + b*16 + n] * CN[(long)n*262144 + j];
    outp[i] = a;
}

__global__ __launch_bounds__(256) void mix_expand(const float* __restrict__ EP){
    long i = (long)blockIdx.x*256 + threadIdx.x;   // over BB*RR*DD
    int b = (int)(i >> 18);
    int j = (int)(i & 262143);
    float aq=0.f, ak=0.f, av=0.f;
#pragma unroll
    for (int n=0;n<16;n++){
        float e = EP[(long)n*262144 + j];
        aq += g_w[1*32 + b*16 + n]*e;
        ak += g_w[2*32 + b*16 + n]*e;
        av += g_w[3*32 + b*16 + n]*e;
    }
    g_eq[i]=aq; g_ek[i]=ak; g_ev[i]=av;
}

// ---------------- generic tiled SGEMM: C = alpha*A*B (+Res) ----------------
// A [M,K] row-major. TRANSB? B stored [N,K] : [K,N]. 64x64x32 tiles, 256 threads.
template<bool TRANSB, bool RESID>
__global__ __launch_bounds__(256) void sgemm(const float* __restrict__ A,
                                             const float* __restrict__ Bm,
                                             const float* __restrict__ Res,
                                             float* __restrict__ C,
                                             int M, int N, int K,
                                             long sA, long sB, long sC, float alpha){
    __shared__ float As[32*68];
    __shared__ float Bs[32*68];
    int bz = blockIdx.z;
    A  += (long)bz*sA;
    Bm += (long)bz*sB;
    C  += (long)bz*sC;
    const float* Rp = RESID ? (Res + (long)bz*sC) : (const float*)0;
    int n0 = blockIdx.x*64, m0 = blockIdx.y*64;
    int tid = threadIdx.x;
    int tr = tid >> 4, tc = tid & 15;
    int la_r = tid >> 3;
    int la_c = (tid & 7) * 4;
    int lb_r = tid >> 4;
    int lb_c = (tid & 15) * 4;
    float acc[4][4];
#pragma unroll
    for (int i=0;i<4;i++)
#pragma unroll
        for (int j=0;j<4;j++) acc[i][j]=0.f;

    for (int k0=0; k0<K; k0+=32){
#pragma unroll
        for (int i=0;i<2;i++){
            int r = la_r + i*32;
            float4 v = *(const float4*)(A + (long)(m0+r)*K + k0 + la_c);
            As[(la_c+0)*68 + r] = v.x;
            As[(la_c+1)*68 + r] = v.y;
            As[(la_c+2)*68 + r] = v.z;
            As[(la_c+3)*68 + r] = v.w;
        }
        if (TRANSB){
#pragma unroll
            for (int i=0;i<2;i++){
                int r = la_r + i*32;   // n index
                float4 v = *(const float4*)(Bm + (long)(n0+r)*K + k0 + la_c);
                Bs[(la_c+0)*68 + r] = v.x;
                Bs[(la_c+1)*68 + r] = v.y;
                Bs[(la_c+2)*68 + r] = v.z;
                Bs[(la_c+3)*68 + r] = v.w;
            }
        } else {
#pragma unroll
            for (int i=0;i<2;i++){
                int r = lb_r + i*16;   // k index
                float4 v = *(const float4*)(Bm + (long)(k0+r)*N + n0 + lb_c);
                *(float4*)&Bs[r*68 + lb_c] = v;
            }
        }
        __syncthreads();
#pragma unroll
        for (int k=0;k<32;k++){
            float4 a4 = *(const float4*)&As[k*68 + tr*4];
            float4 b4 = *(const float4*)&Bs[k*68 + tc*4];
            float a[4] = {a4.x,a4.y,a4.z,a4.w};
            float b[4] = {b4.x,b4.y,b4.z,b4.w};
#pragma unroll
            for (int i=0;i<4;i++)
#pragma unroll
                for (int j=0;j<4;j++)
                    acc[i][j] += a[i]*b[j];
        }
        __syncthreads();
    }
#pragma unroll
    for (int i=0;i<4;i++){
        int m = m0 + tr*4 + i;
        float4 v;
        v.x = acc[i][0]*alpha; v.y = acc[i][1]*alpha;
        v.z = acc[i][2]*alpha; v.w = acc[i][3]*alpha;
        if (RESID){
            float4 rr = *(const float4*)(Rp + (long)m*N + n0 + tc*4);
            v.x += rr.x; v.y += rr.y; v.z += rr.z; v.w += rr.w;
        }
        *(float4*)(C + (long)m*N + n0 + tc*4) = v;
    }
}

// ---------------- fused causal flash attention (fp32) ----------------
// grid (S/64, H, B), 256 threads. thread t: q-row r=t>>2, quarter c=t&3 (16 dims/cols).
#define FA_SMEM (4*64*68*4)
__global__ __launch_bounds__(256) void flash_attn(const float* __restrict__ Qf,
                                                  const float* __restrict__ Kf,
                                                  const float* __restrict__ Vf,
                                                  float* __restrict__ Of){
    extern __shared__ float sm[];
    float* Qs  = sm;               // [64][68]  Qs[r][d]
    float* KsT = sm + 64*68;       // [64][68]  KsT[d][k]
    float* Vs  = sm + 2*64*68;     // [64][68]  Vs[k][d]
    float* Ps  = sm + 3*64*68;     // [64][68]  Ps[r][k]
    int qt = blockIdx.x, hh = blockIdx.y, b = blockIdx.z;
    int q0 = qt*64;
    int tid = threadIdx.x;
    int r = tid>>2, c = tid&3;
    const float* Qbase = Qf + ((long)b*SS + q0)*DD + hh*DH;
#pragma unroll
    for (int j=0;j<4;j++){
        float4 v = *(const float4*)(Qbase + (long)r*DD + c*16 + j*4);
        *(float4*)&Qs[r*68 + c*16 + j*4] = v;
    }
    float o[16];
#pragma unroll
    for (int j=0;j<16;j++) o[j]=0.f;
    float m = -1e30f, l = 0.f;
    int qi = q0 + r;

    for (int k0=0; k0<=q0; k0+=64){
        __syncthreads();
        const float* Kbase = Kf + ((long)b*SS + k0)*DD + hh*DH;
        const float* Vbase = Vf + ((long)b*SS + k0)*DD + hh*DH;
#pragma unroll
        for (int j=0;j<4;j++){
            int d = c*16 + j*4;
            float4 kv = *(const float4*)(Kbase + (long)r*DD + d);
            KsT[(d+0)*68 + r] = kv.x;
            KsT[(d+1)*68 + r] = kv.y;
            KsT[(d+2)*68 + r] = kv.z;
            KsT[(d+3)*68 + r] = kv.w;
            float4 vv = *(const float4*)(Vbase + (long)r*DD + d);
            *(float4*)&Vs[r*68 + d] = vv;
        }
        __syncthreads();
        float s[16];
#pragma unroll
        for (int j=0;j<16;j++) s[j]=0.f;
#pragma unroll 4
        for (int d=0; d<64; d++){
            float qd = Qs[r*68 + d];
            const float* kk = &KsT[d*68 + c*16];
            float4 k0v = *(const float4*)(kk);
            float4 k1v = *(const float4*)(kk+4);
            float4 k2v = *(const float4*)(kk+8);
            float4 k3v = *(const float4*)(kk+12);
            s[0]+=qd*k0v.x;  s[1]+=qd*k0v.y;  s[2]+=qd*k0v.z;  s[3]+=qd*k0v.w;
            s[4]+=qd*k1v.x;  s[5]+=qd*k1v.y;  s[6]+=qd*k1v.z;  s[7]+=qd*k1v.w;
            s[8]+=qd*k2v.x;  s[9]+=qd*k2v.y;  s[10]+=qd*k2v.z; s[11]+=qd*k2v.w;
            s[12]+=qd*k3v.x; s[13]+=qd*k3v.y; s[14]+=qd*k3v.z; s[15]+=qd*k3v.w;
        }
#pragma unroll
        for (int j=0;j<16;j++){
            int ki = k0 + c*16 + j;
            s[j] = (ki <= qi) ? s[j]*0.125f : -1e30f;
        }
        float tmax = s[0];
#pragma unroll
        for (int j=1;j<16;j++) tmax = fmaxf(tmax, s[j]);
        tmax = fmaxf(tmax, __shfl_xor_sync(0xffffffffu, tmax, 1));
        tmax = fmaxf(tmax, __shfl_xor_sync(0xffffffffu, tmax, 2));
        float mnew = fmaxf(m, tmax);
        float corr = __expf(m - mnew);
        float psum = 0.f;
#pragma unroll
        for (int j=0;j<16;j++){
            float p = __expf(s[j]-mnew);
            Ps[r*68 + c*16 + j] = p;
            psum += p;
        }
        psum += __shfl_xor_sync(0xffffffffu, psum, 1);
        psum += __shfl_xor_sync(0xffffffffu, psum, 2);
        l = l*corr + psum;
        m = mnew;
#pragma unroll
        for (int j=0;j<16;j++) o[j] *= corr;
        __syncthreads();
#pragma unroll 4
        for (int k=0;k<64;k++){
            float pv = Ps[r*68 + k];
            const float* vv = &Vs[k*68 + c*16];
            float4 v0 = *(const float4*)(vv);
            float4 v1 = *(const float4*)(vv+4);
            float4 v2 = *(const float4*)(vv+8);
            float4 v3 = *(const float4*)(vv+12);
            o[0]+=pv*v0.x;  o[1]+=pv*v0.y;  o[2]+=pv*v0.z;  o[3]+=pv*v0.w;
            o[4]+=pv*v1.x;  o[5]+=pv*v1.y;  o[6]+=pv*v1.z;  o[7]+=pv*v1.w;
            o[8]+=pv*v2.x;  o[9]+=pv*v2.y;  o[10]+=pv*v2.z; o[11]+=pv*v2.w;
            o[12]+=pv*v3.x; o[13]+=pv*v3.y; o[14]+=pv*v3.z; o[15]+=pv*v3.w;
        }
    }
    float inv = 1.f/l;
    float* Ob = Of + ((long)b*SS + q0 + r)*DD + hh*DH + c*16;
#pragma unroll
    for (int j=0;j<4;j++){
        float4 v;
        v.x = o[j*4+0]*inv; v.y = o[j*4+1]*inv;
        v.z = o[j*4+2]*inv; v.w = o[j*4+3]*inv;
        *(float4*)(Ob + j*4) = v;
    }
}

// ---------------- top-8 over 4096 scores + softmax + gather + residual ----------------
__global__ __launch_bounds__(256) void topk_mem(const float* __restrict__ MS,
                                                const float* __restrict__ KV,
                                                const float* __restrict__ X1,
                                                float* __restrict__ OUT){
    int token = blockIdx.x;
    int tid = threadIdx.x, wid = tid>>5, lane = tid&31;
    __shared__ float sv[NKK];
    __shared__ float wv_s[8];
    __shared__ int   wi_s[8];
    __shared__ float tw[TOPK_N];
    __shared__ int   tix[TOPK_N];
    const float* row = MS + (long)token*NKK;
#pragma unroll
    for (int j=0;j<4;j++)
        *(float4*)&sv[tid*4 + j*1024] = *(const float4*)(row + tid*4 + j*1024);
    __syncthreads();
    for (int it=0; it<TOPK_N; it++){
        float bv = -3.4e38f; int bi = 0;
        for (int i=tid; i<NKK; i+=256){
            float x = sv[i];
            if (x > bv){ bv = x; bi = i; }
        }
#pragma unroll
        for (int off=16; off; off>>=1){
            float ov = __shfl_down_sync(0xffffffffu, bv, off);
            int   oi = __shfl_down_sync(0xffffffffu, bi, off);
            if (ov > bv || (ov == bv && oi < bi)){ bv = ov; bi = oi; }
        }
        if (lane==0){ wv_s[wid]=bv; wi_s[wid]=bi; }
        __syncthreads();
        if (tid==0){
            float BV = wv_s[0]; int BI = wi_s[0];
#pragma unroll
            for (int w=1;w<8;w++)
                if (wv_s[w] > BV || (wv_s[w]==BV && wi_s[w]<BI)){ BV=wv_s[w]; BI=wi_s[w]; }
            tw[it] = BV; tix[it] = BI;
            sv[BI] = -3.4e38f;
        }
        __syncthreads();
    }
    if (tid==0){
        float mx = tw[0], s = 0.f;
#pragma unroll
        for (int k=0;k<TOPK_N;k++){ float e = __expf(tw[k]-mx); tw[k]=e; s+=e; }
        float inv = 1.f/s;
#pragma unroll
        for (int k=0;k<TOPK_N;k++) tw[k] *= inv;
    }
    __syncthreads();
    float4 acc = *(const float4*)(X1 + (long)token*DD + tid*4);
#pragma unroll
    for (int k=0;k<TOPK_N;k++){
        float w = tw[k];
        float4 v = *(const float4*)(KV + (long)tix[k]*DD + tid*4);
        acc.x += w*v.x; acc.y += w*v.y; acc.z += w*v.z; acc.w += w*v.w;
    }
    *(float4*)(OUT + (long)token*DD + tid*4) = acc;
}

// ---------------- host ----------------
extern "C" void kernel_launch(void* const* d_in, const int* in_sizes, int n_in,
                              void* d_out, int out_size){
    const float* x   = (const float*)d_in[0];
    const float* imp = (const float*)d_in[1];
    const float* Wc  = (const float*)d_in[2];
    const float* WQp = (const float*)d_in[3];
    const float* WKp = (const float*)d_in[4];
    const float* WVp = (const float*)d_in[5];
    const float* Wm  = (const float*)d_in[6];
    const float* CN  = (const float*)d_in[7];
    const float* EP  = (const float*)d_in[8];
    const float* KK  = (const float*)d_in[9];
    const float* KV  = (const float*)d_in[10];
    const float* WO  = (const float*)d_in[11];
    const float* g1  = (const float*)d_in[12];
    const float* b1  = (const float*)d_in[13];
    const float* g2  = (const float*)d_in[14];
    const float* b2  = (const float*)d_in[15];
    float* out = (float*)d_out;

    float *nx, *nx2, *h, *Qm, *Q, *Kt, *V, *ao, *x1, *ms, *sc, *mc, *eq, *ek, *ev;
    cudaGetSymbolAddress((void**)&nx,  g_nx);
    cudaGetSymbolAddress((void**)&nx2, g_nx2);
    cudaGetSymbolAddress((void**)&h,   g_h);
    cudaGetSymbolAddress((void**)&Qm,  g_Qm);
    cudaGetSymbolAddress((void**)&Q,   g_Q);
    cudaGetSymbolAddress((void**)&Kt,  g_K);
    cudaGetSymbolAddress((void**)&V,   g_V);
    cudaGetSymbolAddress((void**)&ao,  g_ao);
    cudaGetSymbolAddress((void**)&x1,  g_x1);
    cudaGetSymbolAddress((void**)&ms,  g_ms);
    cudaGetSymbolAddress((void**)&sc,  g_sc);
    cudaGetSymbolAddress((void**)&mc,  g_mc);
    cudaGetSymbolAddress((void**)&eq,  g_eq);
    cudaGetSymbolAddress((void**)&ek,  g_ek);
    cudaGetSymbolAddress((void**)&ev,  g_ev);

    cudaFuncSetAttribute(flash_attn, cudaFuncAttributeMaxDynamicSharedMemorySize, FA_SMEM);

    // ---- attention sub-block ----
    ln_kernel<<<BB*SS, 256>>>(x, g1, b1, nx);
    router_kernel<<<BB*SS, 256>>>(nx, imp, Wc, WQp, WKp, WVp, 4);
    pool_w<<<dim3(64, BB), 256>>>(0, 4);
    norm_w<<<1, 32>>>(0, 4);
    mix_compress<<<2048, 256>>>(CN, sc, 0);
    mix_expand<<<2048, 256>>>(EP);
    // h[b] = nx[b] (2048x1024) * sc[b] (1024x256)
    sgemm<false,false><<<dim3(256/64, SS/64, BB), 256>>>(
        nx, sc, (const float*)0, h, SS, RR, DD,
        (long)SS*DD, (long)DD*RR, (long)SS*RR, 1.f);
    // Q/K/V[b] = h[b] (2048x256) * e*[b] (256x1024)
    sgemm<false,false><<<dim3(DD/64, SS/64, BB), 256>>>(
        h, eq, (const float*)0, Q, SS, DD, RR,
        (long)SS*RR, (long)RR*DD, (long)SS*DD, 1.f);
    sgemm<false,false><<<dim3(DD/64, SS/64, BB), 256>>>(
        h, ek, (const float*)0, Kt, SS, DD, RR,
        (long)SS*RR, (long)RR*DD, (long)SS*DD, 1.f);
    sgemm<false,false><<<dim3(DD/64, SS/64, BB), 256>>>(
        h, ev, (const float*)0, V, SS, DD, RR,
        (long)SS*RR, (long)RR*DD, (long)SS*DD, 1.f);
    flash_attn<<<dim3(SS/64, HH, BB), 256, FA_SMEM>>>(Q, Kt, V, ao);
    // x1 = ao (4096x1024) * WO^T + x
    sgemm<true,true><<<dim3(DD/64, BB*SS/64, 1), 256>>>(
        ao, WO, x, x1, BB*SS, DD, DD, 0L, 0L, 0L, 1.f);

    // ---- memory sub-block ----
    ln_kernel<<<BB*SS, 256>>>(x1, g2, b2, nx2);
    router_kernel<<<BB*SS, 256>>>(nx2, imp, Wm, Wm, Wm, Wm, 1);
    pool_w<<<dim3(16, BB), 256>>>(4, 1);
    norm_w<<<1, 32>>>(4, 1);
    mix_compress<<<2048, 256>>>(CN, mc, 4);
    sgemm<false,false><<<dim3(256/64, SS/64, BB), 256>>>(
        nx2, mc, (const float*)0, Qm, SS, RR, DD,
        (long)SS*DD, (long)DD*RR, (long)SS*RR, 1.f);
    // ms[b] = Qm[b] (2048x256) * KK^T (256x4096), scaled by 1/sqrt(256)
    sgemm<true,false><<<dim3(NKK/64, SS/64, BB), 256>>>(
        Qm, KK, (const float*)0, ms, SS, NKK, KRR,
        (long)SS*KRR, 0L, (long)SS*NKK, 0.0625f);
    topk_mem<<<BB*SS, 256>>>(ms, KV, x1, out);

    (void)in_sizes; (void)n_in; (void)out_size;
}

// round 11
// speedup vs baseline: 2.1195x; 2.1195x over previous
#include <cuda_runtime.h>
#include <cuda_bf16.h>
#include <math.h>

// Problem dims
#define BB 2
#define SS 2048
#define DD 1024
#define HH 16
#define DH 64
#define RR 256
#define NKK 4096
#define KRR 256
#define TOPK_N 8

// ---------------- scratch (device globals; no runtime alloc) ----------------
__device__ float g_nx  [BB*SS*DD];
__device__ float g_nx2 [BB*SS*DD];
__device__ float g_h   [BB*SS*RR];
__device__ float g_Qm  [BB*SS*RR];
__device__ float g_qkv [3*BB*SS*DD];
__device__ float g_ao  [BB*SS*DD];
__device__ float g_x1  [BB*SS*DD];
__device__ float g_ms  [BB*SS*NKK];
__device__ float g_sc  [BB*DD*RR];
__device__ float g_mc  [BB*DD*RR];
__device__ float g_e   [3*BB*RR*DD];
__device__ float g_pref[BB*SS*64];
__device__ float g_w   [5*BB*16];

__device__ __forceinline__ float warp_sum(float v){
#pragma unroll
    for (int o=16;o;o>>=1) v += __shfl_xor_sync(0xffffffffu, v, o);
    return v;
}

// ---------------- LayerNorm ----------------
__global__ __launch_bounds__(256) void ln_kernel(const float* __restrict__ X,
                                                 const float* __restrict__ G,
                                                 const float* __restrict__ Bt,
                                                 float* __restrict__ O){
    int row = blockIdx.x, tid = threadIdx.x;
    const float* xr = X + (long)row*DD + tid*4;
    float4 v = *(const float4*)xr;
    float s = v.x+v.y+v.z+v.w;
    float q = v.x*v.x+v.y*v.y+v.z*v.z+v.w*v.w;
    __shared__ float rs[8], rq[8];
    __shared__ float stats[2];
    s = warp_sum(s); q = warp_sum(q);
    int wid = tid>>5, lane = tid&31;
    if (lane==0){ rs[wid]=s; rq[wid]=q; }
    __syncthreads();
    if (tid==0){
        float Sm=0.f, Qm=0.f;
#pragma unroll
        for (int i=0;i<8;i++){ Sm+=rs[i]; Qm+=rq[i]; }
        float mu  = Sm*(1.f/(float)DD);
        float var = Qm*(1.f/(float)DD) - mu*mu;
        stats[0]=mu; stats[1]=rsqrtf(var + 1e-5f);
    }
    __syncthreads();
    float mu = stats[0], rstd = stats[1];
    float4 g4 = *(const float4*)(G  + tid*4);
    float4 b4 = *(const float4*)(Bt + tid*4);
    float4 o4;
    o4.x = (v.x-mu)*rstd*g4.x + b4.x;
    o4.y = (v.y-mu)*rstd*g4.y + b4.y;
    o4.z = (v.z-mu)*rstd*g4.z + b4.z;
    o4.w = (v.w-mu)*rstd*g4.w + b4.w;
    *(float4*)(O + (long)row*DD + tid*4) = o4;
}

// ---------------- router ----------------
__global__ __launch_bounds__(256) void router_kernel(const float* __restrict__ NX,
                                                     const float* __restrict__ IMP,
                                                     const float* __restrict__ W0,
                                                     const float* __restrict__ W1,
                                                     const float* __restrict__ W2,
                                                     const float* __restrict__ W3,
                                                     int NR){
    int token = blockIdx.x;
    int tid = threadIdx.x, wid = tid>>5, lane = tid&31;
    __shared__ float xs[DD];
    __shared__ float logits[64];
    *(float4*)&xs[tid*4] = *(const float4*)(NX + (long)token*DD + tid*4);
    __syncthreads();
    const float* Ws[4] = {W0,W1,W2,W3};
    for (int l = wid; l < NR*16; l += 8){
        const float* wrow = Ws[l>>4] + (long)(l&15)*DD;
        float p = 0.f;
#pragma unroll
        for (int d0=0; d0<DD; d0+=128){
            float4 xv = *(const float4*)&xs[d0 + lane*4];
            float4 wv = *(const float4*)(wrow + d0 + lane*4);
            p += xv.x*wv.x + xv.y*wv.y + xv.z*wv.z + xv.w*wv.w;
        }
        p = warp_sum(p);
        if (lane==0) logits[l] = p;
    }
    __syncthreads();
    if (tid < NR){
        float im = IMP[token];
        float mx = -1e30f;
#pragma unroll
        for (int n=0;n<16;n++) mx = fmaxf(mx, logits[tid*16+n]);
        float e[16]; float sum = 0.f;
#pragma unroll
        for (int n=0;n<16;n++){ e[n] = __expf(logits[tid*16+n]-mx); sum += e[n]; }
        float inv = im / sum;
#pragma unroll
        for (int n=0;n<16;n++) g_pref[(long)token*64 + tid*16 + n] = e[n]*inv;
    }
}

__global__ __launch_bounds__(256) void pool_w(int base, int NR){
    int ln = blockIdx.x;
    int b  = blockIdx.y;
    int tid = threadIdx.x;
    float s = 0.f;
    for (int t=tid; t<SS; t+=256)
        s += g_pref[((long)(b*SS+t))*64 + ln];
    s = warp_sum(s);
    __shared__ float rs[8];
    if ((tid&31)==0) rs[tid>>5] = s;
    __syncthreads();
    if (tid==0){
        float S=0.f;
#pragma unroll
        for (int i=0;i<8;i++) S += rs[i];
        g_w[(base + (ln>>4))*32 + b*16 + (ln&15)] = S;
    }
    (void)NR;
}

__global__ void norm_w(int base, int NR){
    int i = threadIdx.x;
    if (i < NR*BB){
        int ri = base + i/BB, b = i%BB;
        float s = 0.f;
#pragma unroll
        for (int n=0;n<16;n++) s += g_w[ri*32 + b*16 + n];
        s += 1e-8f;
        float inv = 1.f/s;
#pragma unroll
        for (int n=0;n<16;n++) g_w[ri*32 + b*16 + n] *= inv;
    }
}

// ---------------- expert mixing ----------------
__global__ __launch_bounds__(256) void mix_compress(const float* __restrict__ CN,
                                                    float* __restrict__ outp, int ri){
    long i = (long)blockIdx.x*256 + threadIdx.x;
    int b = (int)(i >> 18);
    int j = (int)(i & 262143);
    float a = 0.f;
#pragma unroll
    for (int n=0;n<16;n++) a += g_w[ri*32 + b*16 + n] * CN[(long)n*262144 + j];
    outp[i] = a;
}

__global__ __launch_bounds__(256) void mix_expand(const float* __restrict__ EP){
    long i = (long)blockIdx.x*256 + threadIdx.x;   // over BB*RR*DD
    int b = (int)(i >> 18);
    int j = (int)(i & 262143);
    float aq=0.f, ak=0.f, av=0.f;
#pragma unroll
    for (int n=0;n<16;n++){
        float e = EP[(long)n*262144 + j];
        aq += g_w[1*32 + b*16 + n]*e;
        ak += g_w[2*32 + b*16 + n]*e;
        av += g_w[3*32 + b*16 + n]*e;
    }
    g_e[(0*BB + b)*262144L + j] = aq;
    g_e[(1*BB + b)*262144L + j] = ak;
    g_e[(2*BB + b)*262144L + j] = av;
}

// ---------------- SGEMM 128x128x16, 8x8 microtile, double-buffered ----------------
// A [M,K] row-major. TRANSB? B stored [N,K] : [K,N]. 256 threads.
template<bool TRANSB, bool RESID>
__global__ __launch_bounds__(256) void sgemm128(const float* __restrict__ A,
                                                const float* __restrict__ Bm,
                                                const float* __restrict__ Res,
                                                float* __restrict__ C,
                                                int M, int N, int K,
                                                long sA, long sB, long sC,
                                                int aMod, float alpha){
    __shared__ float As[2][16*132];
    __shared__ float Bs[2][16*132];
    int bz = blockIdx.z;
    A  += (long)(bz % aMod)*sA;
    Bm += (long)bz*sB;
    C  += (long)bz*sC;
    const float* Rp = RESID ? (Res + (long)bz*sC) : (const float*)0;
    int m0 = blockIdx.y*128, n0 = blockIdx.x*128;
    int tid = threadIdx.x;
    int ty = tid>>4, tx = tid&15;
    int ar = tid>>1;           // 0..127
    int ak = (tid&1)*8;        // 0 / 8
    int bk = tid>>4, bc = (tid&15)*4;

    float acc[8][8];
#pragma unroll
    for (int i=0;i<8;i++)
#pragma unroll
        for (int j=0;j<8;j++) acc[i][j]=0.f;

    float4 ra0, ra1, rb0, rb1;
    const float* Arow = A + (long)(m0+ar)*K;

    // prologue: load tile 0
    ra0 = *(const float4*)(Arow + ak);
    ra1 = *(const float4*)(Arow + ak + 4);
    if (TRANSB){
        const float* Brow = Bm + (long)(n0+ar)*K;
        rb0 = *(const float4*)(Brow + ak);
        rb1 = *(const float4*)(Brow + ak + 4);
    } else {
        rb0 = *(const float4*)(Bm + (long)bk*N + n0 + bc);
        rb1 = *(const float4*)(Bm + (long)bk*N + n0 + bc + 64);
    }
    {
        float* as = &As[0][0];
        as[(ak+0)*132+ar]=ra0.x; as[(ak+1)*132+ar]=ra0.y;
        as[(ak+2)*132+ar]=ra0.z; as[(ak+3)*132+ar]=ra0.w;
        as[(ak+4)*132+ar]=ra1.x; as[(ak+5)*132+ar]=ra1.y;
        as[(ak+6)*132+ar]=ra1.z; as[(ak+7)*132+ar]=ra1.w;
        float* bs = &Bs[0][0];
        if (TRANSB){
            bs[(ak+0)*132+ar]=rb0.x; bs[(ak+1)*132+ar]=rb0.y;
            bs[(ak+2)*132+ar]=rb0.z; bs[(ak+3)*132+ar]=rb0.w;
            bs[(ak+4)*132+ar]=rb1.x; bs[(ak+5)*132+ar]=rb1.y;
            bs[(ak+6)*132+ar]=rb1.z; bs[(ak+7)*132+ar]=rb1.w;
        } else {
            *(float4*)&bs[bk*132 + bc]      = rb0;
            *(float4*)&bs[bk*132 + bc + 64] = rb1;
        }
    }
    __syncthreads();

    int nk = K >> 4;
    for (int kt=0; kt<nk; kt++){
        int buf = kt & 1;
        if (kt+1 < nk){
            int k0 = (kt+1)*16;
            ra0 = *(const float4*)(Arow + k0 + ak);
            ra1 = *(const float4*)(Arow + k0 + ak + 4);
            if (TRANSB){
                const float* Brow = Bm + (long)(n0+ar)*K;
                rb0 = *(const float4*)(Brow + k0 + ak);
                rb1 = *(const float4*)(Brow + k0 + ak + 4);
            } else {
                rb0 = *(const float4*)(Bm + (long)(k0+bk)*N + n0 + bc);
                rb1 = *(const float4*)(Bm + (long)(k0+bk)*N + n0 + bc + 64);
            }
        }
        const float* as = &As[buf][0];
        const float* bs = &Bs[buf][0];
#pragma unroll
        for (int k=0;k<16;k++){
            float4 a0 = *(const float4*)&as[k*132 + ty*8];
            float4 a1 = *(const float4*)&as[k*132 + ty*8 + 4];
            float4 b0 = *(const float4*)&bs[k*132 + tx*8];
            float4 b1 = *(const float4*)&bs[k*132 + tx*8 + 4];
            float a[8] = {a0.x,a0.y,a0.z,a0.w,a1.x,a1.y,a1.z,a1.w};
            float b[8] = {b0.x,b0.y,b0.z,b0.w,b1.x,b1.y,b1.z,b1.w};
#pragma unroll
            for (int i=0;i<8;i++)
#pragma unroll
                for (int j=0;j<8;j++)
                    acc[i][j] += a[i]*b[j];
        }
        if (kt+1 < nk){
            int nbuf = buf ^ 1;
            float* asn = &As[nbuf][0];
            asn[(ak+0)*132+ar]=ra0.x; asn[(ak+1)*132+ar]=ra0.y;
            asn[(ak+2)*132+ar]=ra0.z; asn[(ak+3)*132+ar]=ra0.w;
            asn[(ak+4)*132+ar]=ra1.x; asn[(ak+5)*132+ar]=ra1.y;
            asn[(ak+6)*132+ar]=ra1.z; asn[(ak+7)*132+ar]=ra1.w;
            float* bsn = &Bs[nbuf][0];
            if (TRANSB){
                bsn[(ak+0)*132+ar]=rb0.x; bsn[(ak+1)*132+ar]=rb0.y;
                bsn[(ak+2)*132+ar]=rb0.z; bsn[(ak+3)*132+ar]=rb0.w;
                bsn[(ak+4)*132+ar]=rb1.x; bsn[(ak+5)*132+ar]=rb1.y;
                bsn[(ak+6)*132+ar]=rb1.z; bsn[(ak+7)*132+ar]=rb1.w;
            } else {
                *(float4*)&bsn[bk*132 + bc]      = rb0;
                *(float4*)&bsn[bk*132 + bc + 64] = rb1;
            }
        }
        __syncthreads();
    }

#pragma unroll
    for (int i=0;i<8;i++){
        long crow = m0 + ty*8 + i;
        float4 v0, v1;
        v0.x=acc[i][0]*alpha; v0.y=acc[i][1]*alpha; v0.z=acc[i][2]*alpha; v0.w=acc[i][3]*alpha;
        v1.x=acc[i][4]*alpha; v1.y=acc[i][5]*alpha; v1.z=acc[i][6]*alpha; v1.w=acc[i][7]*alpha;
        if (RESID){
            float4 r0 = *(const float4*)(Rp + crow*N + n0 + tx*8);
            float4 r1 = *(const float4*)(Rp + crow*N + n0 + tx*8 + 4);
            v0.x+=r0.x; v0.y+=r0.y; v0.z+=r0.z; v0.w+=r0.w;
            v1.x+=r1.x; v1.y+=r1.y; v1.z+=r1.z; v1.w+=r1.w;
        }
        *(float4*)(C + crow*N + n0 + tx*8)     = v0;
        *(float4*)(C + crow*N + n0 + tx*8 + 4) = v1;
    }
}

// ---------------- flash attention: 128q x 64k tiles, 8x4 microtile ----------------
#define FA2_SMEM ((64*132 + 64*68 + 64*68 + 64*132)*4)
__global__ __launch_bounds__(256,2) void flash_attn2(const float* __restrict__ Qf,
                                                     const float* __restrict__ Kf,
                                                     const float* __restrict__ Vf,
                                                     float* __restrict__ Of){
    extern __shared__ float sm[];
    float* Qs = sm;              // [64 d][132]  Qs[d][q]
    float* Ks = Qs + 64*132;     // [64 d][68]   Ks[d][k]
    float* Vs = Ks + 64*68;      // [64 k][68]   Vs[k][d]
    float* Ps = Vs + 64*68;      // [64 k][132]  Ps[k][q]
    int qt = 15 - blockIdx.x;    // long blocks first
    int hh = blockIdx.y, b = blockIdx.z;
    int q0 = qt*128;
    int tid = threadIdx.x, ty = tid>>4, tx = tid&15;

    {   // load Q (scaled by 1/sqrt(dh)=0.125)
        int row = tid>>1, db = (tid&1)*32;
        const float* qp = Qf + ((long)b*SS + q0 + row)*DD + hh*DH + db;
#pragma unroll
        for (int u=0;u<8;u++){
            float4 v = *(const float4*)(qp + u*4);
            int d = db + u*4;
            Qs[(d+0)*132+row]=v.x*0.125f; Qs[(d+1)*132+row]=v.y*0.125f;
            Qs[(d+2)*132+row]=v.z*0.125f; Qs[(d+3)*132+row]=v.w*0.125f;
        }
    }
    float o[8][4]; float m[8], l[8];
#pragma unroll
    for (int i=0;i<8;i++){
        m[i]=-1e30f; l[i]=0.f;
#pragma unroll
        for (int j=0;j<4;j++) o[i][j]=0.f;
    }
    int ntiles = qt*2 + 2;
    for (int t=0; t<ntiles; t++){
        int k0 = t*64;
        __syncthreads();
        {   // load K (transposed) and V
            int row = tid>>2, db = (tid&3)*16;
            const float* kp = Kf + ((long)b*SS + k0 + row)*DD + hh*DH + db;
            const float* vp = Vf + ((long)b*SS + k0 + row)*DD + hh*DH + db;
#pragma unroll
            for (int u=0;u<4;u++){
                float4 kv = *(const float4*)(kp + u*4);
                int d = db + u*4;
                Ks[(d+0)*68+row]=kv.x; Ks[(d+1)*68+row]=kv.y;
                Ks[(d+2)*68+row]=kv.z; Ks[(d+3)*68+row]=kv.w;
                float4 vv = *(const float4*)(vp + u*4);
                *(float4*)&Vs[row*68 + d] = vv;
            }
        }
        __syncthreads();
        float s[8][4];
#pragma unroll
        for (int i=0;i<8;i++)
#pragma unroll
            for (int j=0;j<4;j++) s[i][j]=0.f;
#pragma unroll 8
        for (int d=0; d<64; d++){
            float4 qa = *(const float4*)&Qs[d*132 + ty*8];
            float4 qb = *(const float4*)&Qs[d*132 + ty*8 + 4];
            float4 kv = *(const float4*)&Ks[d*68 + tx*4];
            float qv[8] = {qa.x,qa.y,qa.z,qa.w,qb.x,qb.y,qb.z,qb.w};
            float kk[4] = {kv.x,kv.y,kv.z,kv.w};
#pragma unroll
            for (int i=0;i<8;i++)
#pragma unroll
                for (int j=0;j<4;j++)
                    s[i][j] += qv[i]*kk[j];
        }
        if (t >= ntiles-2){
#pragma unroll
            for (int i=0;i<8;i++){
                int qi = q0 + ty*8 + i;
#pragma unroll
                for (int j=0;j<4;j++){
                    int ki = k0 + tx*4 + j;
                    if (ki > qi) s[i][j] = -1e30f;
                }
            }
        }
#pragma unroll
        for (int i=0;i<8;i++){
            float mx = fmaxf(fmaxf(s[i][0],s[i][1]), fmaxf(s[i][2],s[i][3]));
            mx = fmaxf(mx, __shfl_xor_sync(0xffffffffu, mx, 1));
            mx = fmaxf(mx, __shfl_xor_sync(0xffffffffu, mx, 2));
            mx = fmaxf(mx, __shfl_xor_sync(0xffffffffu, mx, 4));
            mx = fmaxf(mx, __shfl_xor_sync(0xffffffffu, mx, 8));
            float mn = fmaxf(m[i], mx);
            float corr = __expf(m[i]-mn);
            m[i] = mn;
            float ps = 0.f;
#pragma unroll
            for (int j=0;j<4;j++){
                float p = __expf(s[i][j]-mn);
                s[i][j]=p; ps+=p;
            }
            ps += __shfl_xor_sync(0xffffffffu, ps, 1);
            ps += __shfl_xor_sync(0xffffffffu, ps, 2);
            ps += __shfl_xor_sync(0xffffffffu, ps, 4);
            ps += __shfl_xor_sync(0xffffffffu, ps, 8);
            l[i] = l[i]*corr + ps;
#pragma unroll
            for (int j=0;j<4;j++) o[i][j] *= corr;
#pragma unroll
            for (int j=0;j<4;j++)
                Ps[(tx*4+j)*132 + ty*8 + i] = s[i][j];
        }
        __syncthreads();
#pragma unroll 8
        for (int k=0;k<64;k++){
            float4 pa = *(const float4*)&Ps[k*132 + ty*8];
            float4 pb = *(const float4*)&Ps[k*132 + ty*8 + 4];
            float4 vv = *(const float4*)&Vs[k*68 + tx*4];
            float pv[8] = {pa.x,pa.y,pa.z,pa.w,pb.x,pb.y,pb.z,pb.w};
            float vr[4] = {vv.x,vv.y,vv.z,vv.w};
#pragma unroll
            for (int i=0;i<8;i++)
#pragma unroll
                for (int j=0;j<4;j++)
                    o[i][j] += pv[i]*vr[j];
        }
    }
#pragma unroll
    for (int i=0;i<8;i++){
        float inv = 1.f/l[i];
        float4 v;
        v.x=o[i][0]*inv; v.y=o[i][1]*inv; v.z=o[i][2]*inv; v.w=o[i][3]*inv;
        *(float4*)(Of + ((long)b*SS + q0 + ty*8 + i)*DD + hh*DH + tx*4) = v;
    }
}

// ---------------- top-8 + softmax + gather + residual ----------------
__global__ __launch_bounds__(256) void topk_mem(const float* __restrict__ MS,
                                                const float* __restrict__ KV,
                                                const float* __restrict__ X1,
                                                float* __restrict__ OUT){
    int token = blockIdx.x;
    int tid = threadIdx.x, wid = tid>>5, lane = tid&31;
    __shared__ float sv[NKK];
    __shared__ float wv_s[8];
    __shared__ int   wi_s[8];
    __shared__ float tw[TOPK_N];
    __shared__ int   tix[TOPK_N];
    const float* row = MS + (long)token*NKK;
#pragma unroll
    for (int j=0;j<4;j++)
        *(float4*)&sv[tid*4 + j*1024] = *(const float4*)(row + tid*4 + j*1024);
    __syncthreads();
    for (int it=0; it<TOPK_N; it++){
        float bv = -3.4e38f; int bi = 0;
        for (int i=tid; i<NKK; i+=256){
            float x = sv[i];
            if (x > bv){ bv = x; bi = i; }
        }
#pragma unroll
        for (int off=16; off; off>>=1){
            float ov = __shfl_down_sync(0xffffffffu, bv, off);
            int   oi = __shfl_down_sync(0xffffffffu, bi, off);
            if (ov > bv || (ov == bv && oi < bi)){ bv = ov; bi = oi; }
        }
        if (lane==0){ wv_s[wid]=bv; wi_s[wid]=bi; }
        __syncthreads();
        if (tid==0){
            float BV = wv_s[0]; int BI = wi_s[0];
#pragma unroll
            for (int w=1;w<8;w++)
                if (wv_s[w] > BV || (wv_s[w]==BV && wi_s[w]<BI)){ BV=wv_s[w]; BI=wi_s[w]; }
            tw[it] = BV; tix[it] = BI;
            sv[BI] = -3.4e38f;
        }
        __syncthreads();
    }
    if (tid==0){
        float mx = tw[0], s = 0.f;
#pragma unroll
        for (int k=0;k<TOPK_N;k++){ float e = __expf(tw[k]-mx); tw[k]=e; s+=e; }
        float inv = 1.f/s;
#pragma unroll
        for (int k=0;k<TOPK_N;k++) tw[k] *= inv;
    }
    __syncthreads();
    float4 acc = *(const float4*)(X1 + (long)token*DD + tid*4);
#pragma unroll
    for (int k=0;k<TOPK_N;k++){
        float w = tw[k];
        float4 v = *(const float4*)(KV + (long)tix[k]*DD + tid*4);
        acc.x += w*v.x; acc.y += w*v.y; acc.z += w*v.z; acc.w += w*v.w;
    }
    *(float4*)(OUT + (long)token*DD + tid*4) = acc;
}

// ---------------- host ----------------
extern "C" void kernel_launch(void* const* d_in, const int* in_sizes, int n_in,
                              void* d_out, int out_size){
    const float* x   = (const float*)d_in[0];
    const float* imp = (const float*)d_in[1];
    const float* Wc  = (const float*)d_in[2];
    const float* WQp = (const float*)d_in[3];
    const float* WKp = (const float*)d_in[4];
    const float* WVp = (const float*)d_in[5];
    const float* Wm  = (const float*)d_in[6];
    const float* CN  = (const float*)d_in[7];
    const float* EP  = (const float*)d_in[8];
    const float* KK  = (const float*)d_in[9];
    const float* KV  = (const float*)d_in[10];
    const float* WO  = (const float*)d_in[11];
    const float* g1  = (const float*)d_in[12];
    const float* b1  = (const float*)d_in[13];
    const float* g2  = (const float*)d_in[14];
    const float* b2  = (const float*)d_in[15];
    float* out = (float*)d_out;

    float *nx, *nx2, *h, *Qm, *qkv, *ao, *x1, *ms, *sc, *mc, *ge;
    cudaGetSymbolAddress((void**)&nx,  g_nx);
    cudaGetSymbolAddress((void**)&nx2, g_nx2);
    cudaGetSymbolAddress((void**)&h,   g_h);
    cudaGetSymbolAddress((void**)&Qm,  g_Qm);
    cudaGetSymbolAddress((void**)&qkv, g_qkv);
    cudaGetSymbolAddress((void**)&ao,  g_ao);
    cudaGetSymbolAddress((void**)&x1,  g_x1);
    cudaGetSymbolAddress((void**)&ms,  g_ms);
    cudaGetSymbolAddress((void**)&sc,  g_sc);
    cudaGetSymbolAddress((void**)&mc,  g_mc);
    cudaGetSymbolAddress((void**)&ge,  g_e);

    cudaFuncSetAttribute(flash_attn2, cudaFuncAttributeMaxDynamicSharedMemorySize, FA2_SMEM);

    // ---- attention sub-block ----
    ln_kernel<<<BB*SS, 256>>>(x, g1, b1, nx);
    router_kernel<<<BB*SS, 256>>>(nx, imp, Wc, WQp, WKp, WVp, 4);
    pool_w<<<dim3(64, BB), 256>>>(0, 4);
    norm_w<<<1, 32>>>(0, 4);
    mix_compress<<<2048, 256>>>(CN, sc, 0);
    mix_expand<<<2048, 256>>>(EP);
    // h[b] = nx[b] (2048x1024) * sc[b] (1024x256)
    sgemm128<false,false><<<dim3(RR/128, SS/128, BB), 256>>>(
        nx, sc, (const float*)0, h, SS, RR, DD,
        (long)SS*DD, (long)DD*RR, (long)SS*RR, 64, 1.f);
    // fused QKV: z = t*BB + b : A = h[b], B = g_e[z], C = qkv[z]
    sgemm128<false,false><<<dim3(DD/128, SS/128, 3*BB), 256>>>(
        h, ge, (const float*)0, qkv, SS, DD, RR,
        (long)SS*RR, (long)RR*DD, (long)SS*DD, BB, 1.f);
    flash_attn2<<<dim3(16, HH, BB), 256, FA2_SMEM>>>(
        qkv, qkv + (long)BB*SS*DD, qkv + 2L*BB*SS*DD, ao);
    // x1 = ao (4096x1024) * WO^T + x
    sgemm128<true,true><<<dim3(DD/128, BB*SS/128, 1), 256>>>(
        ao, WO, x, x1, BB*SS, DD, DD, 0L, 0L, 0L, 1, 1.f);

    // ---- memory sub-block ----
    ln_kernel<<<BB*SS, 256>>>(x1, g2, b2, nx2);
    router_kernel<<<BB*SS, 256>>>(nx2, imp, Wm, Wm, Wm, Wm, 1);
    pool_w<<<dim3(16, BB), 256>>>(4, 1);
    norm_w<<<1, 32>>>(4, 1);
    mix_compress<<<2048, 256>>>(CN, mc, 4);
    sgemm128<false,false><<<dim3(RR/128, SS/128, BB), 256>>>(
        nx2, mc, (const float*)0, Qm, SS, RR, DD,
        (long)SS*DD, (long)DD*RR, (long)SS*RR, 64, 1.f);
    // ms[b] = Qm[b] (2048x256) * KK^T, scaled 1/16
    sgemm128<true,false><<<dim3(NKK/128, SS/128, BB), 256>>>(
        Qm, KK, (const float*)0, ms, SS, NKK, KRR,
        (long)SS*KRR, 0L, (long)SS*NKK, 64, 0.0625f);
    topk_mem<<<BB*SS, 256>>>(ms, KV, x1, out);

    (void)in_sizes; (void)n_in; (void)out_size;
}